// round 13
// baseline (speedup 1.0000x reference)
#include <cuda_runtime.h>
#include <cuda_bf16.h>
#include <cstdint>

// Problem dims
#define SEQ 512
#define BATCH 16
#define EMB 512
#define SB 8192           // SEQ*BATCH rows
#define DFF 2048
#define DSS 128
#define SDEPTH 48
#define SWIDTH 128
#define NHEADS 8
#define HDIM 64

// ---------------- scratch (device globals; no allocation) ----------------
__device__ float g_h1 [SB * EMB];
__device__ float g_qkv[SB * 3 * EMB];
__device__ float g_att[SB * EMB];
__device__ float g_x  [SB * EMB];
__device__ float g_xt [SB * EMB];      // tf32-rounded copy of x
__device__ float g_ht [SB * EMB];      // tf32-rounded copy of hidden
__device__ float g_hpt[SB * EMB];      // tf32-rounded hidden_prev
__device__ float g_stt[SB * SWIDTH];   // tf32-rounded stack top slice
__device__ float g_lg [SB * DSS];
__device__ float g_si [SB * SWIDTH];
__device__ float g_h2 [SB * EMB];
__device__ float g_f1 [SB * DFF];
__device__ float g_wt [3997696];       // tf32-rounded weights pool

// ---------------- helpers ----------------
__device__ __forceinline__ float nonsat_f(float x) {
    float y = x;
#pragma unroll
    for (int i = 0; i < 20; i++) {
        float y2 = y * y;
        y = __fdividef(0.6666666666666666f * y2 * y + x, y2 + 1.0f);
    }
    return y;
}

__device__ __forceinline__ uint32_t to_tf32(float x) {
    uint32_t r;
    asm("cvt.rna.tf32.f32 %0, %1;" : "=r"(r) : "f"(x));
    return r;
}
__device__ __forceinline__ float rtf(float x) { return __uint_as_float(to_tf32(x)); }

__device__ __forceinline__ void mma_tf32(float (&c)[4], const uint32_t (&a)[4], const uint32_t (&b)[2]) {
    asm volatile(
        "mma.sync.aligned.m16n8k8.row.col.f32.tf32.tf32.f32 "
        "{%0,%1,%2,%3},{%4,%5,%6,%7},{%8,%9},{%0,%1,%2,%3};"
        : "+f"(c[0]), "+f"(c[1]), "+f"(c[2]), "+f"(c[3])
        : "r"(a[0]), "r"(a[1]), "r"(a[2]), "r"(a[3]), "r"(b[0]), "r"(b[1]));
}

__device__ __forceinline__ void ldsm4(uint32_t& r0, uint32_t& r1, uint32_t& r2, uint32_t& r3,
                                      uint32_t addr) {
    asm volatile("ldmatrix.sync.aligned.m8n8.x4.shared.b16 {%0,%1,%2,%3}, [%4];"
                 : "=r"(r0), "=r"(r1), "=r"(r2), "=r"(r3) : "r"(addr));
}

__device__ __forceinline__ void cp16(uint32_t dst, const float* src) {
    asm volatile("cp.async.cg.shared.global [%0], [%1], 16;" :: "r"(dst), "l"(src));
}
#define CP_COMMIT() asm volatile("cp.async.commit_group;")
#define CP_WAIT1()  asm volatile("cp.async.wait_group 1;")

// ---------------- pre-round pass: tf32-round tensors into scratch ----------------
struct RoundEntry { const float* src; float* dst; int n; int shift; int mask; int stride; };
struct RoundArgs { RoundEntry e[12]; };

__global__ void __launch_bounds__(256) round_multi(RoundArgs A) {
    const int gs = gridDim.x * blockDim.x;
    const int t0 = blockIdx.x * blockDim.x + threadIdx.x;
#pragma unroll 1
    for (int i = 0; i < 12; i++) {
        const RoundEntry E = A.e[i];
        for (int idx = t0; idx < E.n; idx += gs) {
            int row = idx >> E.shift;
            int col = idx & E.mask;
            E.dst[idx] = rtf(E.src[(size_t)row * E.stride + col]);
        }
    }
}

// ---------------- GEMM: C[M,N] = A[M,K] @ W[N,K]^T + epilogue ----------------
struct GemmArgs {
    const float* A0; const float* A1; const float* A2;
    const float* W0; const float* W1; const float* W2;
    const float* b0; const float* b1; const float* b2;
    const float* res;
    float* C;
    float* C2;
    int M, N, K;
};

// MODE: 0=+bias  1=+bias,relu,round  2=+bias+res(+C2 round)  3=hidden(3src,+3bias,nonsat,+C2)
//       4=logits(2src,nobias)  5=mix(res: 0.5*(res+acc))  6=+bias,nonsat
template<int MODE>
__device__ __forceinline__ const float* addrA(const GemmArgs& P, int grow, int gk) {
    if constexpr (MODE == 3) {
        if (gk < 512) {
            int xr = ((grow & 511) << 4) + (grow >> 9);
            return &P.A0[(size_t)xr * 512 + gk];
        } else if (gk < 1024) {
            return &P.A1[(size_t)grow * 512 + (gk - 512)];
        } else {
            return &P.A2[(size_t)grow * 128 + (gk - 1024)];
        }
    } else if constexpr (MODE == 4) {
        if (gk < 512) return &P.A0[(size_t)grow * 512 + gk];
        int hr = ((grow & 15) << 9) + (grow >> 4);
        return &P.A1[(size_t)hr * 512 + (gk - 512)];
    } else {
        return &P.A0[(size_t)grow * (size_t)P.K + gk];
    }
}

template<int MODE>
__device__ __forceinline__ const float* addrW(const GemmArgs& P, int n, int gk) {
    if constexpr (MODE == 3) {
        if (gk < 512)       return &P.W0[(size_t)n * 512 + gk];
        else if (gk < 1024) return &P.W1[(size_t)n * 512 + (gk - 512)];
        else                return &P.W2[(size_t)n * 128 + (gk - 1024)];
    } else {
        return &P.W0[(size_t)n * (size_t)P.K + gk];
    }
}

// Tile (32*MT) x 128 x 16, 256 threads = 8 warps (2 x 4), 3-stage cp.async ring.
template<int MODE, int MT>
__global__ void __launch_bounds__(256) gemm_tc(GemmArgs P) {
    constexpr int AROWS = 32 * MT;
    constexpr int ALI = MT / 2;
    __shared__ uint32_t As[3][AROWS * 16];
    __shared__ uint32_t Bs[3][2048];

    const int tid  = threadIdx.x;
    const int lane = tid & 31;
    const int warp = tid >> 5;
    const int wm = warp >> 2;
    const int wn = warp & 3;
    const int bn = blockIdx.x, bm = blockIdx.y;
    const int row0 = bm * AROWS, col0 = bn * 128;

    const int r0 = tid >> 2;
    const int c4 = tid & 3;

    const int nst = P.K >> 4;

    int offsA[2], offsB[2];
    uint32_t rA[2], rB[2];
#pragma unroll
    for (int li = 0; li < ALI; li++) {
        int r = r0 + li * 64;
        offsA[li] = r * 16 + ((c4 ^ ((r >> 1) & 3)) << 2);
        rA[li] = row0 + r;
    }
#pragma unroll
    for (int li = 0; li < 2; li++) {
        int r = r0 + li * 64;
        offsB[li] = r * 16 + ((c4 ^ ((r >> 1) & 3)) << 2);
        rB[li] = col0 + r;
    }

    uint32_t sA[3], sB[3];
#pragma unroll
    for (int i = 0; i < 3; i++) {
        sA[i] = (uint32_t)__cvta_generic_to_shared(&As[i][0]);
        sB[i] = (uint32_t)__cvta_generic_to_shared(&Bs[i][0]);
    }

    auto issue = [&](int s, int b) {
        int kt = (s << 4) + c4 * 4;
#pragma unroll
        for (int li = 0; li < ALI; li++)
            cp16(sA[b] + offsA[li] * 4, addrA<MODE>(P, rA[li], kt));
#pragma unroll
        for (int li = 0; li < 2; li++)
            cp16(sB[b] + offsB[li] * 4, addrW<MODE>(P, rB[li], kt));
    };

    issue(0, 0);
    CP_COMMIT();
    if (nst > 1) issue(1, 1);
    CP_COMMIT();

    float acc[MT][4][4];
#pragma unroll
    for (int i = 0; i < MT; i++)
#pragma unroll
        for (int j = 0; j < 4; j++)
#pragma unroll
            for (int e = 0; e < 4; e++) acc[i][j][e] = 0.f;

    const int m_ = lane >> 3, rr = lane & 7;

    int buf = 0, pbuf = 2;
#pragma unroll 1
    for (int s = 0; s < nst; s++) {
        CP_WAIT1();
        __syncthreads();
        if (s + 2 < nst) issue(s + 2, pbuf);
        CP_COMMIT();

#pragma unroll
        for (int ks = 0; ks < 2; ks++) {
            uint32_t af[MT][4];
            uint32_t bf[4][2];
#pragma unroll
            for (int tm = 0; tm < MT; tm++) {
                int row = wm * (16 * MT) + tm * 16 + ((m_ & 1) << 3) + rr;
                int grp = (2 * ks + (m_ >> 1)) ^ ((row >> 1) & 3);
                ldsm4(af[tm][0], af[tm][1], af[tm][2], af[tm][3],
                      sA[buf] + (row * 16 + (grp << 2)) * 4);
            }
#pragma unroll
            for (int tp = 0; tp < 2; tp++) {
                int row = wn * 32 + tp * 16 + ((m_ & 1) << 3) + rr;
                int grp = (2 * ks + (m_ >> 1)) ^ ((row >> 1) & 3);
                ldsm4(bf[2 * tp][0], bf[2 * tp + 1][0], bf[2 * tp][1], bf[2 * tp + 1][1],
                      sB[buf] + (row * 16 + (grp << 2)) * 4);
            }
#pragma unroll
            for (int tm = 0; tm < MT; tm++)
#pragma unroll
                for (int tn = 0; tn < 4; tn++)
                    mma_tf32(acc[tm][tn], af[tm], bf[tn]);
        }
        buf  = (buf == 2)  ? 0 : buf + 1;
        pbuf = (pbuf == 2) ? 0 : pbuf + 1;
    }

    const int g = lane >> 2;
    const int q = lane & 3;
#pragma unroll
    for (int tmi = 0; tmi < MT; tmi++) {
        int rb = row0 + wm * (16 * MT) + tmi * 16;
#pragma unroll
        for (int h2 = 0; h2 < 2; h2++) {
            int gm = rb + g + h2 * 8;
#pragma unroll
            for (int tni = 0; tni < 4; tni++) {
                int gn = col0 + wn * 32 + tni * 8 + q * 2;
                float v0 = acc[tmi][tni][h2 * 2 + 0];
                float v1 = acc[tmi][tni][h2 * 2 + 1];
                if constexpr (MODE == 0) { v0 += P.b0[gn]; v1 += P.b0[gn + 1]; }
                else if constexpr (MODE == 1) {
                    v0 = rtf(fmaxf(v0 + P.b0[gn], 0.f));
                    v1 = rtf(fmaxf(v1 + P.b0[gn + 1], 0.f));
                } else if constexpr (MODE == 2) {
                    const float* rp = &P.res[(size_t)gm * P.N + gn];
                    v0 = v0 + P.b0[gn] + rp[0];
                    v1 = v1 + P.b0[gn + 1] + rp[1];
                } else if constexpr (MODE == 3) {
                    v0 = nonsat_f(v0 + P.b0[gn] + P.b1[gn] + P.b2[gn]);
                    v1 = nonsat_f(v1 + P.b0[gn + 1] + P.b1[gn + 1] + P.b2[gn + 1]);
                } else if constexpr (MODE == 4) {
                    /* raw */
                } else if constexpr (MODE == 5) {
                    const float* rp = &P.res[(size_t)gm * P.N + gn];
                    v0 = 0.5f * (rp[0] + v0);
                    v1 = 0.5f * (rp[1] + v1);
                } else if constexpr (MODE == 6) {
                    v0 = nonsat_f(v0 + P.b0[gn]);
                    v1 = nonsat_f(v1 + P.b0[gn + 1]);
                }
                *(float2*)&P.C[(size_t)gm * P.N + gn] = make_float2(v0, v1);
                if constexpr (MODE == 2 || MODE == 3) {
                    if (P.C2)
                        *(float2*)&P.C2[(size_t)gm * P.N + gn] = make_float2(rtf(v0), rtf(v1));
                }
            }
        }
    }
}

// ---------------- LayerNorm (row of 512), output tf32-rounded ----------------
__global__ void __launch_bounds__(128) ln_kernel(const float* __restrict__ x,
                                                 const float* __restrict__ g,
                                                 const float* __restrict__ b,
                                                 float* __restrict__ out) {
    const int r = blockIdx.x, t = threadIdx.x;
    const float* row = x + (size_t)r * 512;
    float v0 = row[t], v1 = row[t + 128], v2 = row[t + 256], v3 = row[t + 384];
    __shared__ float sh[4];
    float s = v0 + v1 + v2 + v3;
#pragma unroll
    for (int o = 16; o; o >>= 1) s += __shfl_xor_sync(0xffffffffu, s, o);
    if ((t & 31) == 0) sh[t >> 5] = s;
    __syncthreads();
    float mean = (sh[0] + sh[1] + sh[2] + sh[3]) * (1.f / 512.f);
    __syncthreads();
    float d0 = v0 - mean, d1 = v1 - mean, d2 = v2 - mean, d3 = v3 - mean;
    float q = d0 * d0 + d1 * d1 + d2 * d2 + d3 * d3;
#pragma unroll
    for (int o = 16; o; o >>= 1) q += __shfl_xor_sync(0xffffffffu, q, o);
    if ((t & 31) == 0) sh[t >> 5] = q;
    __syncthreads();
    float var = (sh[0] + sh[1] + sh[2] + sh[3]) * (1.f / 512.f);
    float rstd = rsqrtf(var + 1e-5f);
    float* orow = out + (size_t)r * 512;
    orow[t]       = rtf(d0 * rstd * g[t]       + b[t]);
    orow[t + 128] = rtf(d1 * rstd * g[t + 128] + b[t + 128]);
    orow[t + 256] = rtf(d2 * rstd * g[t + 256] + b[t + 256]);
    orow[t + 384] = rtf(d3 * rstd * g[t + 384] + b[t + 384]);
}

// ---------------- Flash attention, tf32 tensor-core + ldmatrix ----------------
#define AP 72
__global__ void __launch_bounds__(256) attn_kernel(const float* __restrict__ qkv,
                                                   const unsigned char* __restrict__ kmask,
                                                   float* __restrict__ out) {
    extern __shared__ float sm[];
    float* Qs   = sm;
    float* Ks   = Qs + 64 * AP;
    float* Vt   = Ks + 64 * AP;
    float* Ps   = Vt + 64 * AP;
    float* Pt   = Ps + 64 * AP;
    float* mrow = Pt + 64 * 68;
    float* lrow = mrow + 64;
    float* rsc  = lrow + 64;
    float* kmf  = rsc + 64;

    const int tid = threadIdx.x;
    const int qt = blockIdx.x;
    const int bh = blockIdx.y;
    const int b = bh >> 3, h = bh & 7;
    const int lane = tid & 31;
    const int warp = tid >> 5;
    const int wrow = warp >> 2;
    const int wcol = warp & 3;
    const int g  = lane >> 2;
    const int kq = lane & 3;
    const int m_ = lane >> 3, rr = lane & 7;

    const uint32_t qs_b = (uint32_t)__cvta_generic_to_shared(Qs);
    const uint32_t ks_b = (uint32_t)__cvta_generic_to_shared(Ks);
    const uint32_t vt_b = (uint32_t)__cvta_generic_to_shared(Vt);
    const uint32_t ps_b = (uint32_t)__cvta_generic_to_shared(Ps);

#pragma unroll
    for (int li = 0; li < 4; li++) {
        int idx = tid + li * 256;
        int g4 = idx & 15, r = idx >> 4;
        const float4 q = *(const float4*)&qkv[(size_t)((qt * 64 + r) * 16 + b) * 1536 + h * 64 + g4 * 4];
        float* d = &Qs[r * AP + ((g4 ^ (r & 7)) << 2)];
        d[0] = rtf(q.x * 0.125f);
        d[1] = rtf(q.y * 0.125f);
        d[2] = rtf(q.z * 0.125f);
        d[3] = rtf(q.w * 0.125f);
    }
    if (tid < 64) { mrow[tid] = -1e30f; lrow[tid] = 0.f; }

    float Oa[2][2][4];
#pragma unroll
    for (int i = 0; i < 2; i++)
#pragma unroll
        for (int j = 0; j < 2; j++)
#pragma unroll
            for (int e = 0; e < 4; e++) Oa[i][j][e] = 0.f;
    __syncthreads();

    const int rb0 = wrow * 32;
    const int cb0 = wcol * 16;

    // ldmatrix lane row/group offsets (same for A and B operands)
    const int lrow_off = ((m_ & 1) << 3) + rr;   // row within 16-row tile
    const int lgrp_off = (m_ >> 1);              // which k-halfgroup

    for (int kt = 0; kt <= qt; kt++) {
#pragma unroll
        for (int li = 0; li < 4; li++) {
            int idx = tid + li * 256;
            int g4 = idx & 15, c = idx >> 4;
            size_t base = (size_t)((kt * 64 + c) * 16 + b) * 1536 + h * 64;
            const float4 kv = *(const float4*)&qkv[base + 512 + g4 * 4];
            float* d = &Ks[c * AP + ((g4 ^ (c & 7)) << 2)];
            d[0] = rtf(kv.x); d[1] = rtf(kv.y); d[2] = rtf(kv.z); d[3] = rtf(kv.w);
        }
#pragma unroll
        for (int li = 0; li < 4; li++) {
            int idx = tid + li * 256;
            int c = idx & 63, d4 = idx >> 6;
            size_t base = (size_t)((kt * 64 + c) * 16 + b) * 1536 + h * 64 + 1024;
            const float4 vv = *(const float4*)&qkv[base + d4 * 4];
            float v[4] = {vv.x, vv.y, vv.z, vv.w};
#pragma unroll
            for (int j = 0; j < 4; j++) {
                int dd = d4 * 4 + j;
                Vt[dd * AP + (((c >> 2) ^ (dd & 7)) << 2) + (c & 3)] = rtf(v[j]);
            }
        }
        if (tid < 64) kmf[tid] = kmask[b * 512 + kt * 64 + tid] ? -1e30f : 0.f;
        __syncthreads();

        // ---- MMA1: S = Q @ K^T (ldmatrix fragments) ----
        float sc[2][2][4];
#pragma unroll
        for (int i = 0; i < 2; i++)
#pragma unroll
            for (int j = 0; j < 2; j++)
#pragma unroll
                for (int e = 0; e < 4; e++) sc[i][j][e] = 0.f;
#pragma unroll
        for (int ks = 0; ks < 8; ks++) {
            uint32_t af[2][4], bf[2][2];
#pragma unroll
            for (int tm = 0; tm < 2; tm++) {
                int row = rb0 + tm * 16 + lrow_off;
                int grp = (2 * ks + lgrp_off) ^ (row & 7);
                ldsm4(af[tm][0], af[tm][1], af[tm][2], af[tm][3],
                      qs_b + (row * AP + grp * 4) * 4);
            }
            {
                int row = cb0 + lrow_off;
                int grp = (2 * ks + lgrp_off) ^ (row & 7);
                ldsm4(bf[0][0], bf[1][0], bf[0][1], bf[1][1],
                      ks_b + (row * AP + grp * 4) * 4);
            }
#pragma unroll
            for (int tm = 0; tm < 2; tm++)
#pragma unroll
                for (int tn = 0; tn < 2; tn++)
                    mma_tf32(sc[tm][tn], af[tm], bf[tn]);
        }

        const bool diag = (kt == qt);
#pragma unroll
        for (int tm = 0; tm < 2; tm++) {
#pragma unroll
            for (int tn = 0; tn < 2; tn++) {
#pragma unroll
                for (int e = 0; e < 4; e++) {
                    int r = rb0 + tm * 16 + g + (e >> 1) * 8;
                    int c = cb0 + tn * 8 + 2 * kq + (e & 1);
                    float val = sc[tm][tn][e] + kmf[c];
                    if (diag && c > r) val = -1e30f;
                    Pt[c * 68 + r] = val;
                }
            }
        }
        __syncthreads();

        {
            int r = tid >> 2, q4 = tid & 3;
            float mx = -1e30f;
#pragma unroll
            for (int cc = 0; cc < 16; cc++) mx = fmaxf(mx, Pt[(q4 * 16 + cc) * 68 + r]);
            mx = fmaxf(mx, __shfl_xor_sync(0xffffffffu, mx, 1));
            mx = fmaxf(mx, __shfl_xor_sync(0xffffffffu, mx, 2));
            float mold = mrow[r];
            float mnew = fmaxf(mold, mx);
            float sum = 0.f;
#pragma unroll
            for (int cc = 0; cc < 16; cc++) {
                int c = q4 * 16 + cc;
                float p = __expf(Pt[c * 68 + r] - mnew);
                Ps[r * AP + (((c >> 2) ^ (r & 7)) << 2) + (c & 3)] = rtf(p);
                sum += p;
            }
            sum += __shfl_xor_sync(0xffffffffu, sum, 1);
            sum += __shfl_xor_sync(0xffffffffu, sum, 2);
            if (q4 == 0) {
                float scale = __expf(mold - mnew);
                mrow[r] = mnew;
                lrow[r] = lrow[r] * scale + sum;
                rsc[r] = scale;
            }
        }
        __syncthreads();

#pragma unroll
        for (int tm = 0; tm < 2; tm++) {
            float s0 = rsc[rb0 + tm * 16 + g];
            float s1 = rsc[rb0 + tm * 16 + g + 8];
#pragma unroll
            for (int tn = 0; tn < 2; tn++) {
                Oa[tm][tn][0] *= s0; Oa[tm][tn][1] *= s0;
                Oa[tm][tn][2] *= s1; Oa[tm][tn][3] *= s1;
            }
        }
        // ---- MMA2: O += P @ V (ldmatrix fragments) ----
#pragma unroll
        for (int ks = 0; ks < 8; ks++) {
            uint32_t af[2][4], bf[2][2];
#pragma unroll
            for (int tm = 0; tm < 2; tm++) {
                int row = rb0 + tm * 16 + lrow_off;
                int grp = (2 * ks + lgrp_off) ^ (row & 7);
                ldsm4(af[tm][0], af[tm][1], af[tm][2], af[tm][3],
                      ps_b + (row * AP + grp * 4) * 4);
            }
            {
                int row = cb0 + lrow_off;
                int grp = (2 * ks + lgrp_off) ^ (row & 7);
                ldsm4(bf[0][0], bf[1][0], bf[0][1], bf[1][1],
                      vt_b + (row * AP + grp * 4) * 4);
            }
#pragma unroll
            for (int tm = 0; tm < 2; tm++)
#pragma unroll
                for (int tn = 0; tn < 2; tn++)
                    mma_tf32(Oa[tm][tn], af[tm], bf[tn]);
        }
        __syncthreads();
    }

#pragma unroll
    for (int tm = 0; tm < 2; tm++) {
#pragma unroll
        for (int e2 = 0; e2 < 2; e2++) {
            int r = rb0 + tm * 16 + g + e2 * 8;
            float inv = __fdividef(1.f, lrow[r]);
#pragma unroll
            for (int tn = 0; tn < 2; tn++) {
                int d = cb0 + tn * 8 + 2 * kq;
                float v0 = rtf(Oa[tm][tn][e2 * 2 + 0] * inv);
                float v1 = rtf(Oa[tm][tn][e2 * 2 + 1] * inv);
                *(float2*)&out[(size_t)((qt * 64 + r) * 16 + b) * 512 + h * 64 + d] =
                    make_float2(v0, v1);
            }
        }
    }
}

// ---------------- softmax over 128 (mixture logits), output tf32-rounded -------
__global__ void __launch_bounds__(128) softmax128_kernel(float* __restrict__ lg) {
    const int r = blockIdx.x, t = threadIdx.x;
    float v = lg[(size_t)r * 128 + t];
    __shared__ float sh[4];
    float m = v;
#pragma unroll
    for (int o = 16; o; o >>= 1) m = fmaxf(m, __shfl_xor_sync(0xffffffffu, m, o));
    if ((t & 31) == 0) sh[t >> 5] = m;
    __syncthreads();
    m = fmaxf(fmaxf(sh[0], sh[1]), fmaxf(sh[2], sh[3]));
    float e = __expf(v - m);
    __syncthreads();
    float s = e;
#pragma unroll
    for (int o = 16; o; o >>= 1) s += __shfl_xor_sync(0xffffffffu, s, o);
    if ((t & 31) == 0) sh[t >> 5] = s;
    __syncthreads();
    s = sh[0] + sh[1] + sh[2] + sh[3];
    lg[(size_t)r * 128 + t] = rtf(e * __fdividef(1.f, s));
}

// ---------------- fused controls + stack update ----------------
__global__ void __launch_bounds__(128) stack_kernel(const float* __restrict__ stack_prev,
                                                    const float* __restrict__ si,
                                                    const float* __restrict__ hidden,
                                                    const float* __restrict__ Aw,
                                                    const float* __restrict__ Ab,
                                                    float* __restrict__ out) {
    const int g = blockIdx.x;
    const int t = threadIdx.x;

    const float* hrow = hidden + (size_t)g * 512;
    float s0 = 0.f, s1 = 0.f, s2 = 0.f;
#pragma unroll
    for (int i = 0; i < 4; i++) {
        int c = t + i * 128;
        float hv = hrow[c];
        s0 += hv * Aw[c];
        s1 += hv * Aw[512 + c];
        s2 += hv * Aw[1024 + c];
    }
    __shared__ float sh[3][4];
    __shared__ float bc[3];
#pragma unroll
    for (int o = 16; o; o >>= 1) {
        s0 += __shfl_xor_sync(0xffffffffu, s0, o);
        s1 += __shfl_xor_sync(0xffffffffu, s1, o);
        s2 += __shfl_xor_sync(0xffffffffu, s2, o);
    }
    if ((t & 31) == 0) { sh[0][t >> 5] = s0; sh[1][t >> 5] = s1; sh[2][t >> 5] = s2; }
    __syncthreads();
    if (t == 0) {
        float c0 = sh[0][0] + sh[0][1] + sh[0][2] + sh[0][3] + Ab[0];
        float c1 = sh[1][0] + sh[1][1] + sh[1][2] + sh[1][3] + Ab[1];
        float c2 = sh[2][0] + sh[2][1] + sh[2][2] + sh[2][3] + Ab[2];
        float m = fmaxf(c0, fmaxf(c1, c2));
        float e0 = __expf(c0 - m), e1 = __expf(c1 - m), e2 = __expf(c2 - m);
        float inv = __fdividef(1.f, e0 + e1 + e2);
        bc[0] = e0 * inv; bc[1] = e1 * inv; bc[2] = e2 * inv;
    }
    __syncthreads();
    const float cpush = bc[0], cpop = bc[1], cnoop = bc[2];

    const float* prev = stack_prev + (size_t)g * (SDEPTH * SWIDTH);
    float* o = out + (size_t)g * (SDEPTH * SWIDTH);
    float pm1 = si[(size_t)g * 128 + t];
    float p0 = prev[t];
#pragma unroll 4
    for (int d = 0; d < SDEPTH; d++) {
        float p1 = (d < SDEPTH - 1) ? prev[(d + 1) * SWIDTH + t] : 0.f;
        o[d * SWIDTH + t] = cnoop * p0 + cpush * pm1 + cpop * p1;
        pm1 = p0;
        p0 = p1;
    }
}

// ---------------- host ----------------
template<int MODE, int MT>
static void launch_gemm(const GemmArgs& P) {
    dim3 grid(P.N / 128, P.M / (32 * MT));
    gemm_tc<MODE, MT><<<grid, 256>>>(P);
}

extern "C" void kernel_launch(void* const* d_in, const int* in_sizes, int n_in,
                              void* d_out, int out_size) {
    const float* x_in        = (const float*)d_in[0];
    const float* hidden_prev = (const float*)d_in[1];
    const float* stack_prev  = (const float*)d_in[2];
    const unsigned char* k_mask = (const unsigned char*)d_in[3];
    const float* in_proj_w  = (const float*)d_in[4];
    const float* in_proj_b  = (const float*)d_in[5];
    const float* out_proj_w = (const float*)d_in[6];
    const float* out_proj_b = (const float*)d_in[7];
    const float* ln1_g = (const float*)d_in[8];
    const float* ln1_b = (const float*)d_in[9];
    const float* ln2_g = (const float*)d_in[10];
    const float* ln2_b = (const float*)d_in[11];
    const float* ff_w1 = (const float*)d_in[12];
    const float* ff_b1 = (const float*)d_in[13];
    const float* ff_w2 = (const float*)d_in[14];
    const float* ff_b2 = (const float*)d_in[15];
    const float* W_w = (const float*)d_in[16];
    const float* W_b = (const float*)d_in[17];
    const float* R_w = (const float*)d_in[18];
    const float* R_b = (const float*)d_in[19];
    const float* P_w = (const float*)d_in[20];
    const float* P_b = (const float*)d_in[21];
    const float* V_w = (const float*)d_in[22];
    const float* U_w = (const float*)d_in[23];
    const float* A_w = (const float*)d_in[24];
    const float* A_b = (const float*)d_in[25];
    const float* D_w = (const float*)d_in[26];
    const float* D_b = (const float*)d_in[27];

    float *h1, *qkvb, *attb, *xb, *xt, *ht, *hpt, *stt, *lg, *si, *h2, *f1, *wt;
    cudaGetSymbolAddress((void**)&h1,  g_h1);
    cudaGetSymbolAddress((void**)&qkvb, g_qkv);
    cudaGetSymbolAddress((void**)&attb, g_att);
    cudaGetSymbolAddress((void**)&xb,  g_x);
    cudaGetSymbolAddress((void**)&xt,  g_xt);
    cudaGetSymbolAddress((void**)&ht,  g_ht);
    cudaGetSymbolAddress((void**)&hpt, g_hpt);
    cudaGetSymbolAddress((void**)&stt, g_stt);
    cudaGetSymbolAddress((void**)&lg,  g_lg);
    cudaGetSymbolAddress((void**)&si,  g_si);
    cudaGetSymbolAddress((void**)&h2,  g_h2);
    cudaGetSymbolAddress((void**)&f1,  g_f1);
    cudaGetSymbolAddress((void**)&wt,  g_wt);

    float* t_inproj = wt + 0;
    float* t_outprj = wt + 786432;
    float* t_Ww     = wt + 1048576;
    float* t_Rw     = wt + 1310720;
    float* t_Pw     = wt + 1572864;
    float* t_Vw     = wt + 1638400;
    float* t_Uw     = wt + 1769472;
    float* t_Dw     = wt + 1835008;
    float* t_ff1    = wt + 1900544;
    float* t_ff2    = wt + 2949120;

    float* out_x      = (float*)d_out;
    float* out_hidden = out_x + (size_t)SB * EMB;
    float* out_stack  = out_hidden + (size_t)SB * EMB;

    const int ATTN_SMEM = (4 * 64 * AP + 64 * 68 + 4 * 64) * (int)sizeof(float);
    cudaFuncSetAttribute(attn_kernel, cudaFuncAttributeMaxDynamicSharedMemorySize, ATTN_SMEM);

    // 0. pre-round weights + hidden_prev + stack top to tf32-exact fp32
    {
        const int FM = 0x3FFFFFFF;
        RoundArgs RA{};
        RA.e[0]  = {in_proj_w,  t_inproj, 786432,  30, FM, 0};
        RA.e[1]  = {out_proj_w, t_outprj, 262144,  30, FM, 0};
        RA.e[2]  = {W_w,        t_Ww,     262144,  30, FM, 0};
        RA.e[3]  = {R_w,        t_Rw,     262144,  30, FM, 0};
        RA.e[4]  = {P_w,        t_Pw,     65536,   30, FM, 0};
        RA.e[5]  = {V_w,        t_Vw,     131072,  30, FM, 0};
        RA.e[6]  = {U_w,        t_Uw,     65536,   30, FM, 0};
        RA.e[7]  = {D_w,        t_Dw,     65536,   30, FM, 0};
        RA.e[8]  = {ff_w1,      t_ff1,    1048576, 30, FM, 0};
        RA.e[9]  = {ff_w2,      t_ff2,    1048576, 30, FM, 0};
        RA.e[10] = {hidden_prev, hpt,     SB * EMB, 30, FM, 0};
        RA.e[11] = {stack_prev,  stt,     SB * SWIDTH, 7, 127, SDEPTH * SWIDTH};
        round_multi<<<2048, 256>>>(RA);
    }

    // 1. LN1
    ln_kernel<<<SB, 128>>>(x_in, ln1_g, ln1_b, h1);

    // 2. QKV projection
    {
        GemmArgs P{};
        P.A0 = h1; P.W0 = t_inproj; P.b0 = in_proj_b; P.C = qkvb;
        P.M = SB; P.N = 3 * EMB; P.K = EMB;
        launch_gemm<0, 4>(P);
    }

    // 3. Attention
    attn_kernel<<<dim3(SEQ / 64, BATCH * NHEADS), 256, ATTN_SMEM>>>(qkvb, k_mask, attb);

    // 4. Output projection + residual -> x + xt
    {
        GemmArgs P{};
        P.A0 = attb; P.W0 = t_outprj; P.b0 = out_proj_b; P.res = x_in;
        P.C = xb; P.C2 = xt;
        P.M = SB; P.N = EMB; P.K = EMB;
        launch_gemm<2, 4>(P);
    }

    // 5. hidden = nonsat(xt@W^T + hpt@R^T + stt@P^T + biases) -> out_hidden + ht
    {
        GemmArgs P{};
        P.A0 = xt; P.A1 = hpt; P.A2 = stt;
        P.W0 = t_Ww; P.W1 = t_Rw; P.W2 = t_Pw;
        P.b0 = W_b; P.b1 = R_b; P.b2 = P_b;
        P.C = out_hidden; P.C2 = ht;
        P.M = SB; P.N = EMB; P.K = 1152;
        launch_gemm<3, 4>(P);
    }

    // 6. logits = [xt | ht^T] @ V_w^T  (N=128 -> MT=2)
    {
        GemmArgs P{};
        P.A0 = xt; P.A1 = ht; P.W0 = t_Vw; P.C = lg;
        P.M = SB; P.N = DSS; P.K = 1024;
        launch_gemm<4, 2>(P);
    }

    // 7. softmax over 128
    softmax128_kernel<<<SB, 128>>>(lg);

    // 8. x = 0.5*(x + p @ U_w^T)
    {
        GemmArgs P{};
        P.A0 = lg; P.W0 = t_Uw; P.res = xb; P.C = xb;
        P.M = SB; P.N = EMB; P.K = DSS;
        launch_gemm<5, 4>(P);
    }

    // 9. stack_inp = nonsat(ht @ D_w^T + D_b)  (N=128 -> MT=2)
    {
        GemmArgs P{};
        P.A0 = ht; P.W0 = t_Dw; P.b0 = D_b; P.C = si;
        P.M = SB; P.N = SWIDTH; P.K = EMB;
        launch_gemm<6, 2>(P);
    }

    // 10. fused controls + stack update
    stack_kernel<<<SB, 128>>>(stack_prev, si, out_hidden, A_w, A_b, out_stack);

    // 11. LN2
    ln_kernel<<<SB, 128>>>(xb, ln2_g, ln2_b, h2);

    // 12. FF1 (relu)
    {
        GemmArgs P{};
        P.A0 = h2; P.W0 = t_ff1; P.b0 = ff_b1; P.C = f1;
        P.M = SB; P.N = DFF; P.K = EMB;
        launch_gemm<1, 4>(P);
    }

    // 13. FF2 + residual -> out_x
    {
        GemmArgs P{};
        P.A0 = f1; P.W0 = t_ff2; P.b0 = ff_b2; P.res = xb; P.C = out_x;
        P.M = SB; P.N = EMB; P.K = DFF;
        launch_gemm<2, 4>(P);
    }
}